// round 16
// baseline (speedup 1.0000x reference)
#include <cuda_runtime.h>
#include <cuda_bf16.h>
#include <cuda_fp16.h>
#include <cstdint>

#define N_NODES 50000
#define N_EDGES 800000
#define EA (N_EDGES + N_NODES)      // 850000 edges incl. self loops
#define M_PAD 50048                  // 391 * 128
#define IN_CH 16
#define HID 64
#define HEADS 4
#define F1 256                       // HEADS*HID
#define OUT_CH 8
#define NEG_SLOPE 0.2f
#define NB_SCAN 49                   // ceil(50000/1024)

// ---------------- device scratch (static; no allocations allowed) ------------
__device__ __align__(16) __half g_h[(size_t)M_PAD * F1];     // h in fp16 (both layers)
__device__ __align__(16) __half g_act1[(size_t)M_PAD * F1];  // act1 fp16 (GEMM2 input)
__device__ __align__(16) float g_asrc[(size_t)M_PAD * HEADS];
__device__ __align__(16) float g_adst[(size_t)M_PAD * HEADS];
__device__ __align__(16) uint32_t g_W2h[F1 * F1 / 2];  // W2^T fp16, packed half2 [n][k/2]
__device__ int   g_rowptr[N_NODES + 1];
__device__ int   g_cursor[N_NODES];
__device__ int   g_count[N_NODES];
__device__ int   g_bsum[NB_SCAN];
__device__ int   g_csr_src[EA];
__device__ int   g_is64;

// ---------------- small helpers ---------------------------------------------
__device__ __forceinline__ float lrelu(float x) { return x > 0.f ? x : NEG_SLOPE * x; }
__device__ __forceinline__ float elu(float x)   { return x > 0.f ? x : expm1f(x); }

__device__ __forceinline__ uint32_t pack_h(float a, float b) {
    __half2 t;
    t.x = __float2half_rn(a);
    t.y = __float2half_rn(b);
    return *(uint32_t*)&t;
}
__device__ __forceinline__ float warp_sum(float v) {
    #pragma unroll
    for (int o = 16; o; o >>= 1) v += __shfl_xor_sync(~0u, v, o);
    return v;
}

// mma.sync m16n8k16 fp16 inputs, fp32 accumulate (sm_80+ PTX)
__device__ __forceinline__ void mma_f16(float* d, const uint32_t* a, const uint32_t* b) {
    asm volatile(
        "mma.sync.aligned.m16n8k16.row.col.f32.f16.f16.f32 "
        "{%0,%1,%2,%3}, {%4,%5,%6,%7}, {%8,%9}, {%0,%1,%2,%3};"
        : "+f"(d[0]), "+f"(d[1]), "+f"(d[2]), "+f"(d[3])
        : "r"(a[0]), "r"(a[1]), "r"(a[2]), "r"(a[3]), "r"(b[0]), "r"(b[1]));
}

// ---------------- init: zero counts + detect dtype (merged) -------------------
__global__ void k_init0(const void* ei) {
    int i = blockIdx.x * blockDim.x + threadIdx.x;
    if (i < N_NODES) g_count[i] = 0;
    if (i == 0) {
        const int* e32 = (const int*)ei;
        bool is64 = true;
        #pragma unroll
        for (int j = 0; j < 16; j++)
            if (e32[2 * j + 1] != 0) is64 = false;
        g_is64 = is64 ? 1 : 0;
    }
}

__device__ __forceinline__ void load_edge(const void* ei, int i, int& s, int& d) {
    if (i < N_EDGES) {
        if (g_is64) {
            const long long* e = (const long long*)ei;
            s = (int)e[i]; d = (int)e[N_EDGES + i];
        } else {
            const int* e = (const int*)ei;
            s = e[i]; d = e[N_EDGES + i];
        }
    } else {
        s = d = i - N_EDGES;   // self loop
    }
}

// ---------------- CSR build --------------------------------------------------
__global__ void k_count(const void* ei) {
    int i = blockIdx.x * blockDim.x + threadIdx.x;
    if (i >= EA) return;
    int s, d; load_edge(ei, i, s, d);
    atomicAdd(&g_count[d], 1);
}

// hierarchical scan stage 1: 49 blocks x 1024 (local exclusive scan + block sums)
__global__ void k_scan1() {
    __shared__ int wsum[32];
    int i = blockIdx.x * 1024 + threadIdx.x;
    int lane = threadIdx.x & 31, wid = threadIdx.x >> 5;
    int v = (i < N_NODES) ? g_count[i] : 0;
    int x = v;
    #pragma unroll
    for (int o = 1; o < 32; o <<= 1) {
        int t = __shfl_up_sync(~0u, x, o);
        if (lane >= o) x += t;
    }
    if (lane == 31) wsum[wid] = x;
    __syncthreads();
    if (wid == 0) {
        int y = wsum[lane];
        #pragma unroll
        for (int o = 1; o < 32; o <<= 1) {
            int t = __shfl_up_sync(~0u, y, o);
            if (lane >= o) y += t;
        }
        wsum[lane] = y;
    }
    __syncthreads();
    int excl = x - v + (wid ? wsum[wid - 1] : 0);
    if (i < N_NODES) g_rowptr[i] = excl;
    if (threadIdx.x == 0) g_bsum[blockIdx.x] = wsum[31];
}

// stage 2+3 merged: every block redundantly scans the 49 block sums in smem
// (removes the serialized single-block k_scan2 launch from the critical chain)
__global__ void k_scan3() {
    __shared__ int sb[NB_SCAN + 1];
    int tid = threadIdx.x;
    if (tid < NB_SCAN) sb[tid] = g_bsum[tid];
    __syncthreads();
    if (tid == 0) {
        int acc = 0;
        #pragma unroll
        for (int b = 0; b < NB_SCAN; b++) { int v = sb[b]; sb[b] = acc; acc += v; }
        sb[NB_SCAN] = acc;
        if (blockIdx.x == 0) g_rowptr[N_NODES] = acc;
    }
    __syncthreads();
    int i = blockIdx.x * blockDim.x + tid;
    if (i >= N_NODES) return;
    int r = g_rowptr[i] + sb[i >> 10];
    g_rowptr[i] = r;
    g_cursor[i] = r;
}

__global__ void k_scatter(const void* ei) {
    int i = blockIdx.x * blockDim.x + threadIdx.x;
    if (i >= EA) return;
    int s, d; load_edge(ei, i, s, d);
    int pos = atomicAdd(&g_cursor[d], 1);
    g_csr_src[pos] = s;
}

// ---------------- W2 transpose -> packed fp16 + pad act1 (merged) ------------
__global__ void k_prep(const float* __restrict__ W2) {
    int i = blockIdx.x * blockDim.x + threadIdx.x;
    if (i < F1 * F1 / 2) {
        int n = i >> 7, kp = i & 127;
        int k = kp * 2;
        float w0 = W2[(size_t)k * F1 + n];
        float w1 = W2[(size_t)(k + 1) * F1 + n];
        g_W2h[n * 128 + kp] = pack_h(w0, w1);
    }
    if (i < (M_PAD - N_NODES) * F1 / 2)
        ((uint32_t*)(g_act1 + (size_t)N_NODES * F1))[i] = 0u;
}

// ---------------- GEMM1 + fused alpha1 ---------------------------------------
__global__ void k_gemm1(const float* __restrict__ x, const float* __restrict__ W1,
                        const float* __restrict__ a_src, const float* __restrict__ a_dst) {
    __shared__ float Ws[16 * 256];
    __shared__ float xs[16 * 16];
    __shared__ float aps[16][8], apd[16][8];
    int tid = threadIdx.x;
    int w = tid >> 5, lane = tid & 31;
    int r0 = blockIdx.x * 16;
    for (int i = tid; i < 16 * 256; i += 256) Ws[i] = W1[i];
    {
        int r = r0 + (tid >> 4), c = tid & 15;
        xs[tid] = (r < N_NODES) ? x[r * IN_CH + c] : 0.f;
    }
    float av = a_src[tid], dv = a_dst[tid];
    __syncthreads();
    for (int rr = 0; rr < 16; rr++) {
        float acc = 0.f;
        #pragma unroll
        for (int k = 0; k < 16; k++) acc += xs[rr * 16 + k] * Ws[k * 256 + tid];
        __half hv16 = __float2half_rn(acc);
        g_h[(size_t)(r0 + rr) * F1 + tid] = hv16;
        float hv = __half2float(hv16);
        float ps = warp_sum(hv * av);
        float pd = warp_sum(hv * dv);
        if (lane == 0) { aps[rr][w] = ps; apd[rr][w] = pd; }
    }
    __syncthreads();
    if (tid < 64) {
        int rr = tid >> 2, hh = tid & 3;
        g_asrc[(size_t)(r0 + rr) * 4 + hh] = aps[rr][hh * 2] + aps[rr][hh * 2 + 1];
        g_adst[(size_t)(r0 + rr) * 4 + hh] = apd[rr][hh * 2] + apd[rr][hh * 2 + 1];
    }
}

// ---------------- edge aggregation: one warp per destination node ------------
// R10 loop body verbatim; 64-thread blocks (2 nodes each).
// LAYER 1: writes act1 (256-wide, packed fp16) to g_act1.
// LAYER 2: head-mean + bias + ELU + fused classifier -> writes out directly.
template <int LAYER>
__global__ void k_edge_agg(const float* __restrict__ bias,
                           const float* __restrict__ Wc,
                           const float* __restrict__ bc,
                           float* __restrict__ out) {
    __shared__ float Ws[512];
    __shared__ float bs[8];
    int tid = threadIdx.x;
    if (LAYER == 2) {
        #pragma unroll
        for (int i = tid; i < 512; i += 64) Ws[i] = Wc[i];
        if (tid < 8) bs[tid] = bc[tid];
        __syncthreads();
    }
    int warp = blockIdx.x * 2 + (tid >> 5);
    int lane = tid & 31;
    if (warp >= N_NODES) return;
    int dst = warp;
    int beg = g_rowptr[dst], end = g_rowptr[dst + 1];
    int hh = lane >> 3;
    float ad = g_adst[dst * 4 + hh];

    float acc[8] = {0, 0, 0, 0, 0, 0, 0, 0};
    float den = 0.f;
    for (int k = beg; k < end; k++) {
        int s = g_csr_src[k];
        float e = lrelu(g_asrc[s * 4 + hh] + ad);
        float w = __expf(e);
        den += w;
        uint4 v = *(const uint4*)(g_h + (size_t)s * F1 + lane * 8);
        float2 f0 = __half22float2(*(__half2*)&v.x);
        float2 f1 = __half22float2(*(__half2*)&v.y);
        float2 f2 = __half22float2(*(__half2*)&v.z);
        float2 f3 = __half22float2(*(__half2*)&v.w);
        acc[0] += f0.x * w; acc[1] += f0.y * w; acc[2] += f1.x * w; acc[3] += f1.y * w;
        acc[4] += f2.x * w; acc[5] += f2.y * w; acc[6] += f3.x * w; acc[7] += f3.y * w;
    }
    float inv = 1.f / den;   // self loop guarantees den > 0

    if (LAYER == 1) {
        int c = lane * 8;
        uint4 o;
        o.x = pack_h(elu(acc[0] * inv + bias[c + 0]), elu(acc[1] * inv + bias[c + 1]));
        o.y = pack_h(elu(acc[2] * inv + bias[c + 2]), elu(acc[3] * inv + bias[c + 3]));
        o.z = pack_h(elu(acc[4] * inv + bias[c + 4]), elu(acc[5] * inv + bias[c + 5]));
        o.w = pack_h(elu(acc[6] * inv + bias[c + 6]), elu(acc[7] * inv + bias[c + 7]));
        *(uint4*)(g_act1 + (size_t)dst * F1 + c) = o;
    } else {
        float v[8];
        #pragma unroll
        for (int j = 0; j < 8; j++) {
            v[j] = acc[j] * inv;
            v[j] += __shfl_xor_sync(~0u, v[j], 8);
            v[j] += __shfl_xor_sync(~0u, v[j], 16);
        }
        // lanes 0-7 now hold act2 channels lane*8..lane*8+7 (pre-mean/bias/elu)
        float p[8] = {0, 0, 0, 0, 0, 0, 0, 0};
        if (lane < 8) {
            int c = lane * 8;
            #pragma unroll
            for (int j = 0; j < 8; j++) {
                float a2 = elu(v[j] * 0.25f + bias[c + j]);
                const float* wr = &Ws[(c + j) * 8];
                #pragma unroll
                for (int o = 0; o < 8; o++) p[o] += a2 * wr[o];
            }
        }
        #pragma unroll
        for (int o = 0; o < 8; o++) {
            p[o] += __shfl_xor_sync(~0u, p[o], 1);
            p[o] += __shfl_xor_sync(~0u, p[o], 2);
            p[o] += __shfl_xor_sync(~0u, p[o], 4);
        }
        if (lane == 0) {
            float4 q0 = {p[0] + bs[0], p[1] + bs[1], p[2] + bs[2], p[3] + bs[3]};
            float4 q1 = {p[4] + bs[4], p[5] + bs[5], p[6] + bs[6], p[7] + bs[7]};
            float4* op = (float4*)(out + (size_t)dst * OUT_CH);
            op[0] = q0; op[1] = q1;
        }
    }
}

// ---------------- GEMM2 (single fp16 mma.sync, double-buffered) + alpha2 -----
// A is pre-packed fp16 (g_act1) — staging is a pure uint4 copy.
// Ping-pong smem buffers: one __syncthreads per k-chunk instead of two.
__global__ void __launch_bounds__(256) k_gemm2_mma(const float* __restrict__ as2,
                                                   const float* __restrict__ ad2) {
    __shared__ uint32_t Ah[2][128][17];
    __shared__ uint32_t Bh[2][128][17];

    int tid = threadIdx.x;
    int warp = tid >> 5, lane = tid & 31;
    int wm = warp & 3, wn = warp >> 2;
    int g = lane >> 2, tg = lane & 3;
    int bx = blockIdx.x;                 // 0..1
    int by = blockIdx.y;                 // 0..390

    float acc[2][8][4];
    #pragma unroll
    for (int i = 0; i < 2; i++)
        #pragma unroll
        for (int j = 0; j < 8; j++)
            #pragma unroll
            for (int q = 0; q < 4; q++) acc[i][j][q] = 0.f;

    int arow = tid >> 1, ahalf = tid & 1;
    const uint4* asrc = (const uint4*)(g_act1 + (size_t)(by * 128 + arow) * F1);
    const uint4* bhsrc = (const uint4*)(g_W2h + (size_t)(bx * 128 + arow) * 128 + ahalf * 8);
    int colb = ahalf * 8;

    // preload chunk 0 into buffer 0
    {
        uint4 a0 = asrc[0 * 4 + ahalf * 2 + 0];
        uint4 a1 = asrc[0 * 4 + ahalf * 2 + 1];
        Ah[0][arow][colb + 0] = a0.x; Ah[0][arow][colb + 1] = a0.y;
        Ah[0][arow][colb + 2] = a0.z; Ah[0][arow][colb + 3] = a0.w;
        Ah[0][arow][colb + 4] = a1.x; Ah[0][arow][colb + 5] = a1.y;
        Ah[0][arow][colb + 6] = a1.z; Ah[0][arow][colb + 7] = a1.w;
        uint4 b0 = bhsrc[0 * 4 + 0], b1 = bhsrc[0 * 4 + 1];
        Bh[0][arow][colb + 0] = b0.x; Bh[0][arow][colb + 1] = b0.y;
        Bh[0][arow][colb + 2] = b0.z; Bh[0][arow][colb + 3] = b0.w;
        Bh[0][arow][colb + 4] = b1.x; Bh[0][arow][colb + 5] = b1.y;
        Bh[0][arow][colb + 6] = b1.z; Bh[0][arow][colb + 7] = b1.w;
    }
    __syncthreads();

    for (int kc = 0; kc < 8; kc++) {
        int cur = kc & 1, nxt = cur ^ 1;
        if (kc < 7) {   // stage next chunk into the other buffer
            uint4 a0 = asrc[(kc + 1) * 4 + ahalf * 2 + 0];
            uint4 a1 = asrc[(kc + 1) * 4 + ahalf * 2 + 1];
            Ah[nxt][arow][colb + 0] = a0.x; Ah[nxt][arow][colb + 1] = a0.y;
            Ah[nxt][arow][colb + 2] = a0.z; Ah[nxt][arow][colb + 3] = a0.w;
            Ah[nxt][arow][colb + 4] = a1.x; Ah[nxt][arow][colb + 5] = a1.y;
            Ah[nxt][arow][colb + 6] = a1.z; Ah[nxt][arow][colb + 7] = a1.w;
            uint4 b0 = bhsrc[(kc + 1) * 4 + 0], b1 = bhsrc[(kc + 1) * 4 + 1];
            Bh[nxt][arow][colb + 0] = b0.x; Bh[nxt][arow][colb + 1] = b0.y;
            Bh[nxt][arow][colb + 2] = b0.z; Bh[nxt][arow][colb + 3] = b0.w;
            Bh[nxt][arow][colb + 4] = b1.x; Bh[nxt][arow][colb + 5] = b1.y;
            Bh[nxt][arow][colb + 6] = b1.z; Bh[nxt][arow][colb + 7] = b1.w;
        }
        #pragma unroll
        for (int ks = 0; ks < 2; ks++) {
            uint32_t af[2][4];
            #pragma unroll
            for (int i = 0; i < 2; i++) {
                int rb = wm * 32 + i * 16;
                af[i][0] = Ah[cur][rb + g][ks * 8 + tg];
                af[i][1] = Ah[cur][rb + g + 8][ks * 8 + tg];
                af[i][2] = Ah[cur][rb + g][ks * 8 + 4 + tg];
                af[i][3] = Ah[cur][rb + g + 8][ks * 8 + 4 + tg];
            }
            uint32_t bf[8][2];
            #pragma unroll
            for (int j = 0; j < 8; j++) {
                int n = wn * 64 + j * 8 + g;
                bf[j][0] = Bh[cur][n][ks * 8 + tg];
                bf[j][1] = Bh[cur][n][ks * 8 + 4 + tg];
            }
            #pragma unroll
            for (int i = 0; i < 2; i++)
                #pragma unroll
                for (int j = 0; j < 8; j++)
                    mma_f16(acc[i][j], af[i], bf[j]);
        }
        __syncthreads();
    }

    // epilogue: write fp16 h2 + fused alpha2 dots for this block's head (2bx+wn)
    float sa[4] = {0, 0, 0, 0}, sd[4] = {0, 0, 0, 0};
    #pragma unroll
    for (int i = 0; i < 2; i++) {
        int row0 = by * 128 + wm * 32 + i * 16 + g;
        #pragma unroll
        for (int j = 0; j < 8; j++) {
            int col = bx * 128 + wn * 64 + j * 8 + tg * 2;
            uint32_t plo = pack_h(acc[i][j][0], acc[i][j][1]);
            uint32_t phi = pack_h(acc[i][j][2], acc[i][j][3]);
            *(uint32_t*)(g_h + (size_t)row0 * F1 + col) = plo;
            *(uint32_t*)(g_h + (size_t)(row0 + 8) * F1 + col) = phi;
            float2 flo = __half22float2(*(__half2*)&plo);
            float2 fhi = __half22float2(*(__half2*)&phi);
            float a0 = as2[col], a1 = as2[col + 1];
            float d0 = ad2[col], d1 = ad2[col + 1];
            sa[i * 2 + 0] += flo.x * a0 + flo.y * a1;
            sd[i * 2 + 0] += flo.x * d0 + flo.y * d1;
            sa[i * 2 + 1] += fhi.x * a0 + fhi.y * a1;
            sd[i * 2 + 1] += fhi.x * d0 + fhi.y * d1;
        }
    }
    #pragma unroll
    for (int q = 0; q < 4; q++) {
        sa[q] += __shfl_xor_sync(~0u, sa[q], 1);
        sa[q] += __shfl_xor_sync(~0u, sa[q], 2);
        sd[q] += __shfl_xor_sync(~0u, sd[q], 1);
        sd[q] += __shfl_xor_sync(~0u, sd[q], 2);
    }
    if (tg == 0) {
        int head = bx * 2 + wn;
        #pragma unroll
        for (int i = 0; i < 2; i++) {
            int r = by * 128 + wm * 32 + i * 16 + g;
            g_asrc[(size_t)r * 4 + head] = sa[i * 2 + 0];
            g_adst[(size_t)r * 4 + head] = sd[i * 2 + 0];
            g_asrc[(size_t)(r + 8) * 4 + head] = sa[i * 2 + 1];
            g_adst[(size_t)(r + 8) * 4 + head] = sd[i * 2 + 1];
        }
    }
}

// ---------------- launch -----------------------------------------------------
extern "C" void kernel_launch(void* const* d_in, const int* in_sizes, int n_in,
                              void* d_out, int out_size) {
    const float* x   = (const float*)d_in[0];
    const void*  ei  = d_in[1];
    const float* W1  = (const float*)d_in[2];
    const float* as1 = (const float*)d_in[3];
    const float* ad1 = (const float*)d_in[4];
    const float* b1  = (const float*)d_in[5];
    const float* W2  = (const float*)d_in[6];
    const float* as2 = (const float*)d_in[7];
    const float* ad2 = (const float*)d_in[8];
    const float* b2  = (const float*)d_in[9];
    const float* Wc  = (const float*)d_in[10];
    const float* bc  = (const float*)d_in[11];
    float* out = (float*)d_out;

    // one-time aux stream + events (host-side objects only; no device memory)
    static cudaStream_t s2 = nullptr;
    static cudaEvent_t evF = nullptr, evJ = nullptr;
    if (!s2) {
        cudaStreamCreate(&s2);
        cudaEventCreateWithFlags(&evF, cudaEventDisableTiming);
        cudaEventCreateWithFlags(&evJ, cudaEventDisableTiming);
    }

    // fork: CSR build chain on s2, concurrent with gemm1(+alpha1)/prep on default
    cudaEventRecord(evF, 0);
    cudaStreamWaitEvent(s2, evF, 0);

    k_init0<<<(N_NODES + 255) / 256, 256, 0, s2>>>(ei);
    k_count<<<(EA + 255) / 256, 256, 0, s2>>>(ei);
    k_scan1<<<NB_SCAN, 1024, 0, s2>>>();
    k_scan3<<<(N_NODES + 255) / 256, 256, 0, s2>>>();
    k_scatter<<<(EA + 255) / 256, 256, 0, s2>>>(ei);

    k_prep<<<(F1 * F1 / 2 + 255) / 256, 256>>>(W2);
    k_gemm1<<<M_PAD / 16, 256>>>(x, W1, as1, ad1);

    // join (CSR + gemm1 both done)
    cudaEventRecord(evJ, s2);
    cudaStreamWaitEvent(0, evJ, 0);

    // layer 1 aggregation -> act1 (fp16); 64-thread blocks (2 nodes each)
    k_edge_agg<1><<<(N_NODES + 1) / 2, 64>>>(b1, Wc, bc, out);

    // layer 2 (gemm2 computes h2 + alpha2 in one pass)
    dim3 g2(2, M_PAD / 128);
    k_gemm2_mma<<<g2, 256>>>(as2, ad2);
    // layer 2 aggregation + fused classifier -> out
    k_edge_agg<2><<<(N_NODES + 1) / 2, 64>>>(b2, Wc, bc, out);
}

// round 17
// speedup vs baseline: 1.0098x; 1.0098x over previous
#include <cuda_runtime.h>
#include <cuda_bf16.h>
#include <cuda_fp16.h>
#include <cstdint>

#define N_NODES 50000
#define N_EDGES 800000
#define EA (N_EDGES + N_NODES)      // 850000 edges incl. self loops
#define M_PAD 50048                  // 391 * 128
#define IN_CH 16
#define HID 64
#define HEADS 4
#define F1 256                       // HEADS*HID
#define OUT_CH 8
#define NEG_SLOPE 0.2f
#define NB_SCAN 49                   // ceil(50000/1024)
#define PREP_W2 (F1 * F1 / 2)                         // 32768 items
#define PREP_PAD ((M_PAD - N_NODES) * F1 / 2)         // 6144 items
#define PREP_TOT (PREP_W2 + PREP_PAD)                 // 38912 items

// ---------------- device scratch (static; no allocations allowed) ------------
__device__ __align__(16) __half g_h[(size_t)M_PAD * F1];     // h in fp16 (both layers)
__device__ __align__(16) __half g_act1[(size_t)M_PAD * F1];  // act1 fp16 (GEMM2 input)
__device__ __align__(16) float g_asrc[(size_t)M_PAD * HEADS];
__device__ __align__(16) float g_adst[(size_t)M_PAD * HEADS];
__device__ __align__(16) uint32_t g_W2h[F1 * F1 / 2];  // W2^T fp16, packed half2 [n][k/2]
__device__ int   g_rowptr[N_NODES + 1];
__device__ int   g_cursor[N_NODES];
__device__ int   g_count[N_NODES];
__device__ int   g_bsum[NB_SCAN];
__device__ int   g_boff[NB_SCAN];
__device__ int   g_csr_src[EA];
__device__ int   g_is64;

// ---------------- small helpers ---------------------------------------------
__device__ __forceinline__ float lrelu(float x) { return x > 0.f ? x : NEG_SLOPE * x; }
__device__ __forceinline__ float elu(float x)   { return x > 0.f ? x : expm1f(x); }

__device__ __forceinline__ uint32_t pack_h(float a, float b) {
    __half2 t;
    t.x = __float2half_rn(a);
    t.y = __float2half_rn(b);
    return *(uint32_t*)&t;
}
__device__ __forceinline__ float warp_sum(float v) {
    #pragma unroll
    for (int o = 16; o; o >>= 1) v += __shfl_xor_sync(~0u, v, o);
    return v;
}

// mma.sync m16n8k16 fp16 inputs, fp32 accumulate (sm_80+ PTX)
__device__ __forceinline__ void mma_f16(float* d, const uint32_t* a, const uint32_t* b) {
    asm volatile(
        "mma.sync.aligned.m16n8k16.row.col.f32.f16.f16.f32 "
        "{%0,%1,%2,%3}, {%4,%5,%6,%7}, {%8,%9}, {%0,%1,%2,%3};"
        : "+f"(d[0]), "+f"(d[1]), "+f"(d[2]), "+f"(d[3])
        : "r"(a[0]), "r"(a[1]), "r"(a[2]), "r"(a[3]), "r"(b[0]), "r"(b[1]));
}

// ---------------- init: zero counts + detect dtype (merged) -------------------
__global__ void k_init0(const void* ei) {
    int i = blockIdx.x * blockDim.x + threadIdx.x;
    if (i < N_NODES) g_count[i] = 0;
    if (i == 0) {
        const int* e32 = (const int*)ei;
        bool is64 = true;
        #pragma unroll
        for (int j = 0; j < 16; j++)
            if (e32[2 * j + 1] != 0) is64 = false;
        g_is64 = is64 ? 1 : 0;
    }
}

__device__ __forceinline__ void load_edge(const void* ei, int i, int& s, int& d) {
    if (i < N_EDGES) {
        if (g_is64) {
            const long long* e = (const long long*)ei;
            s = (int)e[i]; d = (int)e[N_EDGES + i];
        } else {
            const int* e = (const int*)ei;
            s = e[i]; d = e[N_EDGES + i];
        }
    } else {
        s = d = i - N_EDGES;   // self loop
    }
}

// ---------------- CSR build --------------------------------------------------
__global__ void k_count(const void* ei) {
    int i = blockIdx.x * blockDim.x + threadIdx.x;
    if (i >= EA) return;
    int s, d; load_edge(ei, i, s, d);
    atomicAdd(&g_count[d], 1);
}

// hierarchical scan: 49 blocks x 1024
__global__ void k_scan1() {
    __shared__ int wsum[32];
    int i = blockIdx.x * 1024 + threadIdx.x;
    int lane = threadIdx.x & 31, wid = threadIdx.x >> 5;
    int v = (i < N_NODES) ? g_count[i] : 0;
    int x = v;
    #pragma unroll
    for (int o = 1; o < 32; o <<= 1) {
        int t = __shfl_up_sync(~0u, x, o);
        if (lane >= o) x += t;
    }
    if (lane == 31) wsum[wid] = x;
    __syncthreads();
    if (wid == 0) {
        int y = wsum[lane];
        #pragma unroll
        for (int o = 1; o < 32; o <<= 1) {
            int t = __shfl_up_sync(~0u, y, o);
            if (lane >= o) y += t;
        }
        wsum[lane] = y;
    }
    __syncthreads();
    int excl = x - v + (wid ? wsum[wid - 1] : 0);
    if (i < N_NODES) g_rowptr[i] = excl;
    if (threadIdx.x == 0) g_bsum[blockIdx.x] = wsum[31];
}

__global__ void k_scan2() {   // 64 threads, 1 block
    __shared__ int s[64];
    int t = threadIdx.x;
    s[t] = (t < NB_SCAN) ? g_bsum[t] : 0;
    __syncthreads();
    if (t == 0) {
        int acc = 0;
        for (int b = 0; b < NB_SCAN; b++) { int v = s[b]; s[b] = acc; acc += v; }
        g_rowptr[N_NODES] = acc;
    }
    __syncthreads();
    if (t < NB_SCAN) g_boff[t] = s[t];
}

__global__ void k_scan3() {
    int i = blockIdx.x * blockDim.x + threadIdx.x;
    if (i >= N_NODES) return;
    int r = g_rowptr[i] + g_boff[i >> 10];
    g_rowptr[i] = r;
    g_cursor[i] = r;
}

__global__ void k_scatter(const void* ei) {
    int i = blockIdx.x * blockDim.x + threadIdx.x;
    if (i >= EA) return;
    int s, d; load_edge(ei, i, s, d);
    int pos = atomicAdd(&g_cursor[d], 1);
    g_csr_src[pos] = s;
}

// ---------------- GEMM1 + fused alpha1 (+ merged W2-split / act1-pad) --------
__global__ void k_gemm1(const float* __restrict__ x, const float* __restrict__ W1,
                        const float* __restrict__ a_src, const float* __restrict__ a_dst,
                        const float* __restrict__ W2) {
    __shared__ float Ws[16 * 256];
    __shared__ float xs[16 * 16];
    __shared__ float aps[16][8], apd[16][8];
    int tid = threadIdx.x;
    int w = tid >> 5, lane = tid & 31;
    int r0 = blockIdx.x * 16;

    // merged prep: first 152 blocks also handle W2 transpose->fp16 + act1 pad
    {
        int pi = blockIdx.x * 256 + tid;
        if (pi < PREP_W2) {
            int n = pi >> 7, kp = pi & 127;
            int k = kp * 2;
            float w0 = W2[(size_t)k * F1 + n];
            float w1 = W2[(size_t)(k + 1) * F1 + n];
            g_W2h[n * 128 + kp] = pack_h(w0, w1);
        } else if (pi < PREP_TOT) {
            ((uint32_t*)(g_act1 + (size_t)N_NODES * F1))[pi - PREP_W2] = 0u;
        }
    }

    for (int i = tid; i < 16 * 256; i += 256) Ws[i] = W1[i];
    {
        int r = r0 + (tid >> 4), c = tid & 15;
        xs[tid] = (r < N_NODES) ? x[r * IN_CH + c] : 0.f;
    }
    float av = a_src[tid], dv = a_dst[tid];
    __syncthreads();
    for (int rr = 0; rr < 16; rr++) {
        float acc = 0.f;
        #pragma unroll
        for (int k = 0; k < 16; k++) acc += xs[rr * 16 + k] * Ws[k * 256 + tid];
        __half hv16 = __float2half_rn(acc);
        g_h[(size_t)(r0 + rr) * F1 + tid] = hv16;
        float hv = __half2float(hv16);
        float ps = warp_sum(hv * av);
        float pd = warp_sum(hv * dv);
        if (lane == 0) { aps[rr][w] = ps; apd[rr][w] = pd; }
    }
    __syncthreads();
    if (tid < 64) {
        int rr = tid >> 2, hh = tid & 3;
        g_asrc[(size_t)(r0 + rr) * 4 + hh] = aps[rr][hh * 2] + aps[rr][hh * 2 + 1];
        g_adst[(size_t)(r0 + rr) * 4 + hh] = apd[rr][hh * 2] + apd[rr][hh * 2 + 1];
    }
}

// ---------------- edge aggregation: one warp per destination node ------------
// R10 loop body verbatim; 64-thread blocks (2 nodes each).
// LAYER 1: writes act1 (256-wide, packed fp16) to g_act1.
// LAYER 2: head-mean + bias + ELU + fused classifier -> writes out directly.
template <int LAYER>
__global__ void k_edge_agg(const float* __restrict__ bias,
                           const float* __restrict__ Wc,
                           const float* __restrict__ bc,
                           float* __restrict__ out) {
    __shared__ float Ws[512];
    __shared__ float bs[8];
    int tid = threadIdx.x;
    if (LAYER == 2) {
        #pragma unroll
        for (int i = tid; i < 512; i += 64) Ws[i] = Wc[i];
        if (tid < 8) bs[tid] = bc[tid];
        __syncthreads();
    }
    int warp = blockIdx.x * 2 + (tid >> 5);
    int lane = tid & 31;
    if (warp >= N_NODES) return;
    int dst = warp;
    int beg = g_rowptr[dst], end = g_rowptr[dst + 1];
    int hh = lane >> 3;
    float ad = g_adst[dst * 4 + hh];

    float acc[8] = {0, 0, 0, 0, 0, 0, 0, 0};
    float den = 0.f;
    for (int k = beg; k < end; k++) {
        int s = g_csr_src[k];
        float e = lrelu(g_asrc[s * 4 + hh] + ad);
        float w = __expf(e);
        den += w;
        uint4 v = *(const uint4*)(g_h + (size_t)s * F1 + lane * 8);
        float2 f0 = __half22float2(*(__half2*)&v.x);
        float2 f1 = __half22float2(*(__half2*)&v.y);
        float2 f2 = __half22float2(*(__half2*)&v.z);
        float2 f3 = __half22float2(*(__half2*)&v.w);
        acc[0] += f0.x * w; acc[1] += f0.y * w; acc[2] += f1.x * w; acc[3] += f1.y * w;
        acc[4] += f2.x * w; acc[5] += f2.y * w; acc[6] += f3.x * w; acc[7] += f3.y * w;
    }
    float inv = 1.f / den;   // self loop guarantees den > 0

    if (LAYER == 1) {
        int c = lane * 8;
        uint4 o;
        o.x = pack_h(elu(acc[0] * inv + bias[c + 0]), elu(acc[1] * inv + bias[c + 1]));
        o.y = pack_h(elu(acc[2] * inv + bias[c + 2]), elu(acc[3] * inv + bias[c + 3]));
        o.z = pack_h(elu(acc[4] * inv + bias[c + 4]), elu(acc[5] * inv + bias[c + 5]));
        o.w = pack_h(elu(acc[6] * inv + bias[c + 6]), elu(acc[7] * inv + bias[c + 7]));
        *(uint4*)(g_act1 + (size_t)dst * F1 + c) = o;
    } else {
        float v[8];
        #pragma unroll
        for (int j = 0; j < 8; j++) {
            v[j] = acc[j] * inv;
            v[j] += __shfl_xor_sync(~0u, v[j], 8);
            v[j] += __shfl_xor_sync(~0u, v[j], 16);
        }
        // lanes 0-7 now hold act2 channels lane*8..lane*8+7 (pre-mean/bias/elu)
        float p[8] = {0, 0, 0, 0, 0, 0, 0, 0};
        if (lane < 8) {
            int c = lane * 8;
            #pragma unroll
            for (int j = 0; j < 8; j++) {
                float a2 = elu(v[j] * 0.25f + bias[c + j]);
                const float* wr = &Ws[(c + j) * 8];
                #pragma unroll
                for (int o = 0; o < 8; o++) p[o] += a2 * wr[o];
            }
        }
        #pragma unroll
        for (int o = 0; o < 8; o++) {
            p[o] += __shfl_xor_sync(~0u, p[o], 1);
            p[o] += __shfl_xor_sync(~0u, p[o], 2);
            p[o] += __shfl_xor_sync(~0u, p[o], 4);
        }
        if (lane == 0) {
            float4 q0 = {p[0] + bs[0], p[1] + bs[1], p[2] + bs[2], p[3] + bs[3]};
            float4 q1 = {p[4] + bs[4], p[5] + bs[5], p[6] + bs[6], p[7] + bs[7]};
            float4* op = (float4*)(out + (size_t)dst * OUT_CH);
            op[0] = q0; op[1] = q1;
        }
    }
}

// ---------------- GEMM2 (single fp16 mma.sync) + fused alpha2 ----------------
// A is pre-packed fp16 (g_act1) — staging is a pure uint4 copy.
__global__ void __launch_bounds__(256) k_gemm2_mma(const float* __restrict__ as2,
                                                   const float* __restrict__ ad2) {
    __shared__ uint32_t Ah[128][17];
    __shared__ uint32_t Bh[128][17];

    int tid = threadIdx.x;
    int warp = tid >> 5, lane = tid & 31;
    int wm = warp & 3, wn = warp >> 2;
    int g = lane >> 2, tg = lane & 3;
    int bx = blockIdx.x;                 // 0..1
    int by = blockIdx.y;                 // 0..390

    float acc[2][8][4];
    #pragma unroll
    for (int i = 0; i < 2; i++)
        #pragma unroll
        for (int j = 0; j < 8; j++)
            #pragma unroll
            for (int q = 0; q < 4; q++) acc[i][j][q] = 0.f;

    int arow = tid >> 1, ahalf = tid & 1;
    const uint4* asrc = (const uint4*)(g_act1 + (size_t)(by * 128 + arow) * F1);
    const uint4* bhsrc = (const uint4*)(g_W2h + (size_t)(bx * 128 + arow) * 128 + ahalf * 8);

    for (int kc = 0; kc < 8; kc++) {
        // stage A (direct fp16 copy)
        {
            uint4 v0 = asrc[kc * 4 + ahalf * 2 + 0];
            uint4 v1 = asrc[kc * 4 + ahalf * 2 + 1];
            int col = ahalf * 8;
            Ah[arow][col + 0] = v0.x; Ah[arow][col + 1] = v0.y;
            Ah[arow][col + 2] = v0.z; Ah[arow][col + 3] = v0.w;
            Ah[arow][col + 4] = v1.x; Ah[arow][col + 5] = v1.y;
            Ah[arow][col + 6] = v1.z; Ah[arow][col + 7] = v1.w;
        }
        // stage B (pre-converted fp16)
        {
            uint4 v0 = bhsrc[kc * 4 + 0], v1 = bhsrc[kc * 4 + 1];
            int col = ahalf * 8;
            Bh[arow][col + 0] = v0.x; Bh[arow][col + 1] = v0.y;
            Bh[arow][col + 2] = v0.z; Bh[arow][col + 3] = v0.w;
            Bh[arow][col + 4] = v1.x; Bh[arow][col + 5] = v1.y;
            Bh[arow][col + 6] = v1.z; Bh[arow][col + 7] = v1.w;
        }
        __syncthreads();

        #pragma unroll
        for (int ks = 0; ks < 2; ks++) {
            uint32_t af[2][4];
            #pragma unroll
            for (int i = 0; i < 2; i++) {
                int rb = wm * 32 + i * 16;
                af[i][0] = Ah[rb + g][ks * 8 + tg];
                af[i][1] = Ah[rb + g + 8][ks * 8 + tg];
                af[i][2] = Ah[rb + g][ks * 8 + 4 + tg];
                af[i][3] = Ah[rb + g + 8][ks * 8 + 4 + tg];
            }
            uint32_t bf[8][2];
            #pragma unroll
            for (int j = 0; j < 8; j++) {
                int n = wn * 64 + j * 8 + g;
                bf[j][0] = Bh[n][ks * 8 + tg];
                bf[j][1] = Bh[n][ks * 8 + 4 + tg];
            }
            #pragma unroll
            for (int i = 0; i < 2; i++)
                #pragma unroll
                for (int j = 0; j < 8; j++)
                    mma_f16(acc[i][j], af[i], bf[j]);
        }
        __syncthreads();
    }

    // epilogue: write fp16 h2 + fused alpha2 dots for this block's head (2bx+wn)
    float sa[4] = {0, 0, 0, 0}, sd[4] = {0, 0, 0, 0};
    #pragma unroll
    for (int i = 0; i < 2; i++) {
        int row0 = by * 128 + wm * 32 + i * 16 + g;
        #pragma unroll
        for (int j = 0; j < 8; j++) {
            int col = bx * 128 + wn * 64 + j * 8 + tg * 2;
            uint32_t plo = pack_h(acc[i][j][0], acc[i][j][1]);
            uint32_t phi = pack_h(acc[i][j][2], acc[i][j][3]);
            *(uint32_t*)(g_h + (size_t)row0 * F1 + col) = plo;
            *(uint32_t*)(g_h + (size_t)(row0 + 8) * F1 + col) = phi;
            float2 flo = __half22float2(*(__half2*)&plo);
            float2 fhi = __half22float2(*(__half2*)&phi);
            float a0 = as2[col], a1 = as2[col + 1];
            float d0 = ad2[col], d1 = ad2[col + 1];
            sa[i * 2 + 0] += flo.x * a0 + flo.y * a1;
            sd[i * 2 + 0] += flo.x * d0 + flo.y * d1;
            sa[i * 2 + 1] += fhi.x * a0 + fhi.y * a1;
            sd[i * 2 + 1] += fhi.x * d0 + fhi.y * d1;
        }
    }
    #pragma unroll
    for (int q = 0; q < 4; q++) {
        sa[q] += __shfl_xor_sync(~0u, sa[q], 1);
        sa[q] += __shfl_xor_sync(~0u, sa[q], 2);
        sd[q] += __shfl_xor_sync(~0u, sd[q], 1);
        sd[q] += __shfl_xor_sync(~0u, sd[q], 2);
    }
    if (tg == 0) {
        int head = bx * 2 + wn;
        #pragma unroll
        for (int i = 0; i < 2; i++) {
            int r = by * 128 + wm * 32 + i * 16 + g;
            g_asrc[(size_t)r * 4 + head] = sa[i * 2 + 0];
            g_adst[(size_t)r * 4 + head] = sd[i * 2 + 0];
            g_asrc[(size_t)(r + 8) * 4 + head] = sa[i * 2 + 1];
            g_adst[(size_t)(r + 8) * 4 + head] = sd[i * 2 + 1];
        }
    }
}

// ---------------- launch -----------------------------------------------------
extern "C" void kernel_launch(void* const* d_in, const int* in_sizes, int n_in,
                              void* d_out, int out_size) {
    const float* x   = (const float*)d_in[0];
    const void*  ei  = d_in[1];
    const float* W1  = (const float*)d_in[2];
    const float* as1 = (const float*)d_in[3];
    const float* ad1 = (const float*)d_in[4];
    const float* b1  = (const float*)d_in[5];
    const float* W2  = (const float*)d_in[6];
    const float* as2 = (const float*)d_in[7];
    const float* ad2 = (const float*)d_in[8];
    const float* b2  = (const float*)d_in[9];
    const float* Wc  = (const float*)d_in[10];
    const float* bc  = (const float*)d_in[11];
    float* out = (float*)d_out;

    // one-time aux stream + events (host-side objects only; no device memory)
    static cudaStream_t s2 = nullptr;
    static cudaEvent_t evF = nullptr, evJ = nullptr;
    if (!s2) {
        cudaStreamCreate(&s2);
        cudaEventCreateWithFlags(&evF, cudaEventDisableTiming);
        cudaEventCreateWithFlags(&evJ, cudaEventDisableTiming);
    }

    // fork: CSR build chain on s2, concurrent with gemm1(+alpha1+prep) on default
    cudaEventRecord(evF, 0);
    cudaStreamWaitEvent(s2, evF, 0);

    k_init0<<<(N_NODES + 255) / 256, 256, 0, s2>>>(ei);
    k_count<<<(EA + 255) / 256, 256, 0, s2>>>(ei);
    k_scan1<<<NB_SCAN, 1024, 0, s2>>>();
    k_scan2<<<1, 64, 0, s2>>>();
    k_scan3<<<(N_NODES + 255) / 256, 256, 0, s2>>>();
    k_scatter<<<(EA + 255) / 256, 256, 0, s2>>>(ei);

    k_gemm1<<<M_PAD / 16, 256>>>(x, W1, as1, ad1, W2);

    // join (CSR + gemm1 both done)
    cudaEventRecord(evJ, s2);
    cudaStreamWaitEvent(0, evJ, 0);

    // layer 1 aggregation -> act1 (fp16); 64-thread blocks (2 nodes each)
    k_edge_agg<1><<<(N_NODES + 1) / 2, 64>>>(b1, Wc, bc, out);

    // layer 2 (gemm2 computes h2 + alpha2 in one pass)
    dim3 g2(2, M_PAD / 128);
    k_gemm2_mma<<<g2, 256>>>(as2, ad2);
    // layer 2 aggregation + fused classifier -> out
    k_edge_agg<2><<<(N_NODES + 1) / 2, 64>>>(b2, Wc, bc, out);
}